// round 5
// baseline (speedup 1.0000x reference)
#include <cuda_runtime.h>
#include <cuda_bf16.h>
#include <cstdint>

typedef unsigned long long ull;

// Problem constants
#define BATCH 8
#define CIN 128
#define COUT 128
#define HW 4096            // 64*64
#define PLANE 524288       // CIN*HW floats per batch
#define NPIX 32768         // BATCH*HW
#define K2 9

// Scratch (device globals: allocation-free per harness rules)
__device__ float g_xT[BATCH * HW * CIN];     // NHWC transpose of x
__device__ float g_off[NPIX * 18];           // offsets, [p][18]
__device__ float g_wT[K2 * CIN * COUT];      // w_conv as [tap][ci][co]

#define BAR_SYNC(id, cnt) \
    asm volatile("bar.sync %0, %1;" :: "r"(id), "r"(cnt) : "memory")
#define BAR_ARRIVE(id, cnt) \
    asm volatile("bar.arrive %0, %1;" :: "r"(id), "r"(cnt) : "memory")
#define MEMBAR_CTA() asm volatile("membar.cta;" ::: "memory")
#define FFMA2(acc, a, b) \
    asm("fma.rn.f32x2 %0, %1, %2, %0;" : "+l"(acc) : "l"(a), "l"(b))
#define DUP64(d, f) asm("mov.b64 %0, {%1, %1};" : "=l"(d) : "f"(f))

// ---------------------------------------------------------------------------
// Kernel 1: NCHW -> NHWC transpose of x
// ---------------------------------------------------------------------------
__global__ void dcb_transpose_kernel(const float* __restrict__ x) {
    __shared__ float tile[32][33];
    int b   = blockIdx.z;
    int ci0 = blockIdx.y * 32;
    int p0  = blockIdx.x * 32;
    int tx = threadIdx.x, ty = threadIdx.y;   // 32 x 8
    const float* xb = x + (size_t)b * PLANE;
    #pragma unroll
    for (int k = 0; k < 32; k += 8)
        tile[ty + k][tx] = xb[(ci0 + ty + k) * HW + p0 + tx];
    __syncthreads();
    float* xTb = g_xT + (size_t)b * PLANE;
    #pragma unroll
    for (int k = 0; k < 32; k += 8)
        xTb[(p0 + ty + k) * CIN + ci0 + tx] = tile[tx][ty + k];
}

// ---------------------------------------------------------------------------
// Kernel 2: w_conv [o][i][ky][kx] -> g_wT [tap][i][o]
// ---------------------------------------------------------------------------
__global__ void dcb_wprep_kernel(const float* __restrict__ wc) {
    int m = blockIdx.x * 256 + threadIdx.x;
    if (m < K2 * CIN * COUT) {
        int tap = m / (CIN * COUT);
        int r   = m - tap * (CIN * COUT);
        int i   = r >> 7;
        int o   = r & 127;
        g_wT[m] = wc[o * (CIN * K2) + i * K2 + tap];
    }
}

// ---------------------------------------------------------------------------
// Kernel 3: offset conv, weights hoisted over 4 pixels.
// smem: ws2[tap][cpair(9)][ci(128)] of float2 = 82944 B
// ---------------------------------------------------------------------------
__global__ __launch_bounds__(256) void dcb_offset_kernel(const float* __restrict__ wofs) {
    extern __shared__ float ws[];
    float2* ws2 = (float2*)ws;
    int tid = threadIdx.x;
    for (int idx = tid; idx < K2 * 9 * CIN; idx += 256) {
        int tap = idx / (9 * CIN);
        int r   = idx - tap * (9 * CIN);
        int cp  = r >> 7;
        int ci  = r & 127;
        float w0 = wofs[(2 * cp)     * (CIN * K2) + ci * K2 + tap];
        float w1 = wofs[(2 * cp + 1) * (CIN * K2) + ci * K2 + tap];
        ws2[(tap * 9 + cp) * 128 + ci] = make_float2(w0, w1);
    }
    __syncthreads();

    int lane = tid & 31;
    int warp = tid >> 5;
    int wg = blockIdx.x * 8 + warp;          // 16 pixels per warp-group
    int ci4 = lane * 4;

    for (int q4 = 0; q4 < 4; q4++) {
        int pbase = wg * 16 + q4 * 4;
        int b   = pbase >> 12;
        const float* xb = g_xT + (size_t)b * PLANE;

        ull acc2[4][9];
        #pragma unroll
        for (int j = 0; j < 4; j++)
            #pragma unroll
            for (int c = 0; c < 9; c++) acc2[j][c] = 0ull;

        #pragma unroll
        for (int tap = 0; tap < 9; tap++) {
            ull ax[4][4];
            #pragma unroll
            for (int j = 0; j < 4; j++) {
                int pix = (pbase + j) & 4095;
                int y   = pix >> 6;
                int x0  = pix & 63;
                int yy = y - 1 + tap / 3;
                int xx = x0 - 1 + tap % 3;
                float4 xv = make_float4(0.f, 0.f, 0.f, 0.f);
                if (yy >= 0 && yy <= 63 && xx >= 0 && xx <= 63)
                    xv = *(const float4*)&xb[(yy * 64 + xx) * CIN + ci4];
                DUP64(ax[j][0], xv.x);
                DUP64(ax[j][1], xv.y);
                DUP64(ax[j][2], xv.z);
                DUP64(ax[j][3], xv.w);
            }
            #pragma unroll
            for (int cp = 0; cp < 9; cp++) {
                const ulonglong2* wp =
                    (const ulonglong2*)(ws2 + (tap * 9 + cp) * 128 + ci4);
                ulonglong2 wA = wp[0];
                ulonglong2 wB = wp[1];
                #pragma unroll
                for (int j = 0; j < 4; j++) {
                    FFMA2(acc2[j][cp], ax[j][0], wA.x);
                    FFMA2(acc2[j][cp], ax[j][1], wA.y);
                    FFMA2(acc2[j][cp], ax[j][2], wB.x);
                    FFMA2(acc2[j][cp], ax[j][3], wB.y);
                }
            }
        }
        #pragma unroll
        for (int j = 0; j < 4; j++) {
            float acc[18];
            #pragma unroll
            for (int cp = 0; cp < 9; cp++)
                asm("mov.b64 {%0, %1}, %2;"
                    : "=f"(acc[2 * cp]), "=f"(acc[2 * cp + 1]) : "l"(acc2[j][cp]));
            #pragma unroll
            for (int c = 0; c < 18; c++) {
                #pragma unroll
                for (int s = 16; s > 0; s >>= 1)
                    acc[c] += __shfl_xor_sync(0xffffffffu, acc[c], s);
            }
            if (lane < 18) {
                float v = 0.f;
                #pragma unroll
                for (int c = 0; c < 18; c++) if (lane == c) v = acc[c];
                g_off[(pbase + j) * 18 + lane] = v;
            }
        }
    }
}

// ---------------------------------------------------------------------------
// Kernel 4: deformable gather + FFMA2 GEMM, warp-specialized.
// Tile 64 px x 128 co; 512 threads: warps 0-7 produce, 8-15 consume.
// SMEM map (bytes):
//   v_dup bufs:  2 x 64px x 1040B     = 133120    (u64 {v,v} per ci, 16B row pad)
//   w tile:      133120 + 64KB halves = 198656
//   m_idx:       198656 (1024)   m_w: 199680 (1024)  -> total 200704
// ---------------------------------------------------------------------------
#define VROWB    1040
#define VBUFB    66560
#define SM_W     133120
#define SM_MIDX  198656
#define SM_MW    199680
#define SMEM_DEF 200704

__global__ __launch_bounds__(512, 1) void dcb_deform_kernel(float* __restrict__ out) {
    extern __shared__ char sm[];
    int tid  = threadIdx.x;
    int wid  = tid >> 5;
    int lane = tid & 31;

    int p0    = blockIdx.x * 64;
    int b     = p0 >> 12;
    int bbase = b << 19;                     // b * PLANE
    int pix0  = p0 & 4095;
    const float* __restrict__ xb = g_xT + bbase;

    int*   m_idx = (int*)(sm + SM_MIDX);
    float* m_w   = (float*)(sm + SM_MW);

    if (wid < 8) {
        // ================= PRODUCER =================
        int ci4 = lane * 4;
        for (int tap = 0; tap < 9; tap++) {
            // meta for 64 pixels (warps 0-1)
            if (tid < 64) {
                int j   = tid;
                int p   = p0 + j;
                int pix = pix0 + j;
                int y   = pix >> 6;
                int xx  = pix & 63;
                float dy = g_off[p * 18 + tap * 2];
                float dx = g_off[p * 18 + tap * 2 + 1];
                float py = (float)(y - 1 + tap / 3) + dy;
                float px = (float)(xx - 1 + tap % 3) + dx;
                float y0f = floorf(py), x0f = floorf(px);
                float fy = py - y0f, fx = px - x0f;
                float vy0 = (y0f >= 0.f  && y0f <= 63.f) ? 1.f : 0.f;
                float vy1 = (y0f >= -1.f && y0f <= 62.f) ? 1.f : 0.f;
                float vx0 = (x0f >= 0.f  && x0f <= 63.f) ? 1.f : 0.f;
                float vx1 = (x0f >= -1.f && x0f <= 62.f) ? 1.f : 0.f;
                int yi0 = (int)fminf(fmaxf(y0f,       0.f), 63.f);
                int yi1 = (int)fminf(fmaxf(y0f + 1.f, 0.f), 63.f);
                int xi0 = (int)fminf(fmaxf(x0f,       0.f), 63.f);
                int xi1 = (int)fminf(fmaxf(x0f + 1.f, 0.f), 63.f);
                m_idx[j * 4 + 0] = (yi0 * 64 + xi0) << 7;
                m_idx[j * 4 + 1] = (yi0 * 64 + xi1) << 7;
                m_idx[j * 4 + 2] = (yi1 * 64 + xi0) << 7;
                m_idx[j * 4 + 3] = (yi1 * 64 + xi1) << 7;
                m_w[j * 4 + 0] = (1.f - fy) * (1.f - fx) * vy0 * vx0;
                m_w[j * 4 + 1] = (1.f - fy) * fx         * vy0 * vx1;
                m_w[j * 4 + 2] = fy         * (1.f - fx) * vy1 * vx0;
                m_w[j * 4 + 3] = fy         * fx         * vy1 * vx1;
            }
            BAR_SYNC(5, 256);                 // meta ready (producers only)

            // gather 8 px per warp into v_dup[buf]
            char* vb = sm + (tap & 1) * VBUFB;
            #pragma unroll
            for (int q = 0; q < 8; q++) {
                int j = wid * 8 + q;
                int4   mi = *(const int4*)  &m_idx[j * 4];
                float4 mw = *(const float4*)&m_w[j * 4];
                float4 c0 = *(const float4*)&xb[mi.x + ci4];
                float4 c1 = *(const float4*)&xb[mi.y + ci4];
                float4 c2 = *(const float4*)&xb[mi.z + ci4];
                float4 c3 = *(const float4*)&xb[mi.w + ci4];
                float4 v;
                v.x = mw.x * c0.x + mw.y * c1.x + mw.z * c2.x + mw.w * c3.x;
                v.y = mw.x * c0.y + mw.y * c1.y + mw.z * c2.y + mw.w * c3.y;
                v.z = mw.x * c0.z + mw.y * c1.z + mw.z * c2.z + mw.w * c3.z;
                v.w = mw.x * c0.w + mw.y * c1.w + mw.z * c2.w + mw.w * c3.w;
                char* dst = vb + j * VROWB + ci4 * 8;
                *(float4*)(dst)      = make_float4(v.x, v.x, v.y, v.y);
                *(float4*)(dst + 16) = make_float4(v.z, v.z, v.w, v.w);
            }
            BAR_SYNC(6, 256);                 // all gathers done (protect m_idx)

            // stage W half0 (ci 0..63) after consumers freed it
            if (tap) BAR_SYNC(1, 512);
            {
                const float4* src = (const float4*)(g_wT + tap * 16384);
                float4* dst = (float4*)(sm + SM_W);
                #pragma unroll
                for (int t = 0; t < 8; t++) dst[tid + t * 256] = src[tid + t * 256];
            }
            MEMBAR_CTA();
            BAR_ARRIVE(3, 512);               // v[tap] + w-half0 ready

            // stage W half1 after consumers done with ALL of tap-1
            if (tap) BAR_SYNC(2, 512);
            {
                const float4* src = (const float4*)(g_wT + tap * 16384 + 8192);
                float4* dst = (float4*)(sm + SM_W + 32768);
                #pragma unroll
                for (int t = 0; t < 8; t++) dst[tid + t * 256] = src[tid + t * 256];
            }
            MEMBAR_CTA();
            BAR_ARRIVE(4, 512);               // w-half1 ready
        }
        BAR_SYNC(1, 512);                     // drain consumer arrivals (tap 8)
        BAR_SYNC(2, 512);
    } else {
        // ================= CONSUMER =================
        int cw = wid - 8;
        int pxblock = (cw & 3) * 16;
        int coblock = (cw >> 2) * 64;
        int pg = lane >> 3;
        int cg = lane & 7;

        ull acc[16];
        #pragma unroll
        for (int i = 0; i < 16; i++) acc[i] = 0ull;

        const char* wp0 = sm + SM_W + coblock * 4 + cg * 16;

        for (int tap = 0; tap < 9; tap++) {
            const char* ap = sm + (tap & 1) * VBUFB + (pxblock + pg) * VROWB;
            #pragma unroll
            for (int h = 0; h < 2; h++) {
                BAR_SYNC(3 + h, 512);         // half h staged
                const char* wp = wp0 + h * 32768;
                const char* ah = ap + h * 512;
                #pragma unroll 8
                for (int ci = 0; ci < 64; ci++) {
                    ull a0 = *(const ull*)(ah + 0 * (4 * VROWB) + ci * 8);
                    ull a1 = *(const ull*)(ah + 1 * (4 * VROWB) + ci * 8);
                    ull a2 = *(const ull*)(ah + 2 * (4 * VROWB) + ci * 8);
                    ull a3 = *(const ull*)(ah + 3 * (4 * VROWB) + ci * 8);
                    ulonglong2 bA = *(const ulonglong2*)(wp + ci * 512);
                    ulonglong2 bB = *(const ulonglong2*)(wp + ci * 512 + 128);
                    FFMA2(acc[0],  a0, bA.x); FFMA2(acc[1],  a0, bA.y);
                    FFMA2(acc[2],  a0, bB.x); FFMA2(acc[3],  a0, bB.y);
                    FFMA2(acc[4],  a1, bA.x); FFMA2(acc[5],  a1, bA.y);
                    FFMA2(acc[6],  a1, bB.x); FFMA2(acc[7],  a1, bB.y);
                    FFMA2(acc[8],  a2, bA.x); FFMA2(acc[9],  a2, bA.y);
                    FFMA2(acc[10], a2, bB.x); FFMA2(acc[11], a2, bB.y);
                    FFMA2(acc[12], a3, bA.x); FFMA2(acc[13], a3, bA.y);
                    FFMA2(acc[14], a3, bB.x); FFMA2(acc[15], a3, bB.y);
                }
                BAR_ARRIVE(1 + h, 512);       // half h of w free / tap done
            }
        }

        // stash acc for epilogue in registers; transposed store below
        __syncthreads();                      // join producers (barrier A)
        float* s_out = (float*)sm;            // [128 co][68] padded
        #pragma unroll
        for (int jj = 0; jj < 4; jj++) {
            int pxr = pxblock + pg + jj * 4;
            #pragma unroll
            for (int kk = 0; kk < 4; kk++) {
                float lo, hi;
                asm("mov.b64 {%0, %1}, %2;" : "=f"(lo), "=f"(hi) : "l"(acc[jj * 4 + kk]));
                int co = coblock + (kk >> 1) * 32 + cg * 4 + (kk & 1) * 2;
                s_out[co * 68 + pxr]       = lo;
                s_out[(co + 1) * 68 + pxr] = hi;
            }
        }
        __syncthreads();                      // barrier B
        goto copyout;
    }
    __syncthreads();                          // producers: barrier A
    __syncthreads();                          // producers: barrier B
copyout:
    {
        float* s_out = (float*)sm;
        int co   = tid >> 2;
        int part = tid & 3;
        const float4* src = (const float4*)(s_out + co * 68 + part * 16);
        float4* dst = (float4*)(out + bbase + co * HW + pix0 + part * 16);
        #pragma unroll
        for (int i = 0; i < 4; i++) dst[i] = src[i];
    }
}

// ---------------------------------------------------------------------------
extern "C" void kernel_launch(void* const* d_in, const int* in_sizes, int n_in,
                              void* d_out, int out_size) {
    const float* x = nullptr;
    const float* wofs = nullptr;
    const float* wconv = nullptr;
    for (int i = 0; i < n_in; i++) {
        if      (in_sizes[i] == BATCH * CIN * HW) x     = (const float*)d_in[i];
        else if (in_sizes[i] == 18 * CIN * K2)    wofs  = (const float*)d_in[i];
        else if (in_sizes[i] == COUT * CIN * K2)  wconv = (const float*)d_in[i];
    }
    float* out = (float*)d_out;

    cudaFuncSetAttribute(dcb_offset_kernel,
                         cudaFuncAttributeMaxDynamicSharedMemorySize, 82944);
    cudaFuncSetAttribute(dcb_deform_kernel,
                         cudaFuncAttributeMaxDynamicSharedMemorySize, SMEM_DEF);

    dim3 tb(32, 8);
    dim3 tg(HW / 32, CIN / 32, BATCH);
    dcb_transpose_kernel<<<tg, tb>>>(x);

    dcb_wprep_kernel<<<(K2 * CIN * COUT + 255) / 256, 256>>>(wconv);

    dcb_offset_kernel<<<256, 256, 82944>>>(wofs);

    dcb_deform_kernel<<<NPIX / 64, 512, SMEM_DEF>>>(out);
}